// round 2
// baseline (speedup 1.0000x reference)
#include <cuda_runtime.h>
#include <cstdint>

#define NB 8
#define NS 1024
#define ND 1024
#define NH 16
#define NDH 64
#define ROWS (NB * NS)  // 8192

typedef unsigned long long u64;

// Scratch (allocation-free rule: __device__ globals)
__device__ float g_qkv[(size_t)ROWS * 3 * ND];  // [8192][3072]
__device__ float g_att[(size_t)ROWS * ND];      // [8192][1024]

__device__ __forceinline__ uint32_t f2tf(float x) {
    uint32_t u;
    asm("cvt.rna.tf32.f32 %0, %1;" : "=r"(u) : "f"(x));
    return u;
}
__device__ __forceinline__ void cp_async16(void* smem, const void* gmem) {
    uint32_t s = (uint32_t)__cvta_generic_to_shared(smem);
    asm volatile("cp.async.cg.shared.global [%0], [%1], 16;\n" :: "r"(s), "l"(gmem));
}
__device__ __forceinline__ void cp_commit() { asm volatile("cp.async.commit_group;\n"); }
__device__ __forceinline__ void cp_wait0()  { asm volatile("cp.async.wait_group 0;\n"); }

// Packed f32x2 helpers (Blackwell FFMA2 — only reachable via PTX)
__device__ __forceinline__ u64 pack2(float lo, float hi) {
    u64 r; asm("mov.b64 %0, {%1, %2};" : "=l"(r) : "f"(lo), "f"(hi)); return r;
}
__device__ __forceinline__ void unpack2(u64 v, float& lo, float& hi) {
    asm("mov.b64 {%0, %1}, %2;" : "=f"(lo), "=f"(hi) : "l"(v));
}
__device__ __forceinline__ u64 fma2(u64 a, u64 b, u64 c) {
    u64 d; asm("fma.rn.f32x2 %0, %1, %2, %3;" : "=l"(d) : "l"(a), "l"(b), "l"(c)); return d;
}
__device__ __forceinline__ u64 mul2(u64 a, u64 b) {
    u64 d; asm("mul.rn.f32x2 %0, %1, %2;" : "=l"(d) : "l"(a), "l"(b)); return d;
}

// ---------------------------------------------------------------------------
// C[M,N] = A[M,K] @ B[K,N], all row-major fp32, TF32 tensor-core mma.
// BM=128, BN=128, BK=16; 256 threads = 8 warps (2x4), warp tile 64x32.
// ---------------------------------------------------------------------------
__global__ __launch_bounds__(256) void gemm_tf32(
    const float* __restrict__ A, const float* __restrict__ B,
    float* __restrict__ C, int M, int N, int K)
{
    constexpr int BM = 128, BN = 128, BK = 16;
    __shared__ __align__(16) float As[2][BM][BK + 4];   // stride 20 floats (80B, 16B-mult)
    __shared__ __align__(16) float Bs[2][BK][BN + 8];   // stride 136 floats (544B, 16B-mult)

    const int tid  = threadIdx.x;
    const int bm   = blockIdx.y * BM;
    const int bn   = blockIdx.x * BN;
    const int warp = tid >> 5, lane = tid & 31;
    const int wm   = (warp & 1) * 64;
    const int wn   = (warp >> 1) * 32;
    const int gr   = lane >> 2;      // groupID 0..7
    const int gc   = lane & 3;       // threadID_in_group 0..3

    float acc[4][4][4];
    #pragma unroll
    for (int mf = 0; mf < 4; mf++)
        #pragma unroll
        for (int nf = 0; nf < 4; nf++)
            #pragma unroll
            for (int i = 0; i < 4; i++)
                acc[mf][nf][i] = 0.f;

    auto load_tile = [&](int t, int buf) {
        #pragma unroll
        for (int i = 0; i < 2; i++) {
            int idx = tid + 256 * i;             // 0..511
            int ra = idx >> 2, ca = (idx & 3) << 2;       // A: 128 rows x 4 float4
            cp_async16(&As[buf][ra][ca],
                       A + (size_t)(bm + ra) * K + t * BK + ca);
            int rb = idx >> 5, cb = (idx & 31) << 2;      // B: 16 rows x 32 float4
            cp_async16(&Bs[buf][rb][cb],
                       B + (size_t)(t * BK + rb) * N + bn + cb);
        }
        cp_commit();
    };

    const int NT = K / BK;
    load_tile(0, 0);

    for (int t = 0; t < NT; t++) {
        const int buf = t & 1;
        cp_wait0();
        __syncthreads();
        if (t + 1 < NT) load_tile(t + 1, buf ^ 1);

        #pragma unroll
        for (int ks = 0; ks < BK; ks += 8) {
            uint32_t afr[4][4], bfr[4][2];
            #pragma unroll
            for (int mf = 0; mf < 4; mf++) {
                int row = wm + mf * 16;
                afr[mf][0] = f2tf(As[buf][row + gr    ][ks + gc    ]);
                afr[mf][1] = f2tf(As[buf][row + gr + 8][ks + gc    ]);
                afr[mf][2] = f2tf(As[buf][row + gr    ][ks + gc + 4]);
                afr[mf][3] = f2tf(As[buf][row + gr + 8][ks + gc + 4]);
            }
            #pragma unroll
            for (int nf = 0; nf < 4; nf++) {
                int col = wn + nf * 8 + gr;
                bfr[nf][0] = f2tf(Bs[buf][ks + gc    ][col]);
                bfr[nf][1] = f2tf(Bs[buf][ks + gc + 4][col]);
            }
            #pragma unroll
            for (int mf = 0; mf < 4; mf++)
                #pragma unroll
                for (int nf = 0; nf < 4; nf++) {
                    asm volatile(
                        "mma.sync.aligned.m16n8k8.row.col.f32.tf32.tf32.f32 "
                        "{%0,%1,%2,%3}, {%4,%5,%6,%7}, {%8,%9}, {%0,%1,%2,%3};\n"
                        : "+f"(acc[mf][nf][0]), "+f"(acc[mf][nf][1]),
                          "+f"(acc[mf][nf][2]), "+f"(acc[mf][nf][3])
                        : "r"(afr[mf][0]), "r"(afr[mf][1]),
                          "r"(afr[mf][2]), "r"(afr[mf][3]),
                          "r"(bfr[nf][0]), "r"(bfr[nf][1]));
                }
        }
        // single sync per iter: top-of-next-iter sync protects buffer reuse
    }

    // Epilogue: c0,c1 at (gr, 2*gc), c2,c3 at (gr+8, 2*gc)
    #pragma unroll
    for (int mf = 0; mf < 4; mf++)
        #pragma unroll
        for (int nf = 0; nf < 4; nf++) {
            size_t row0 = (size_t)(bm + wm + mf * 16 + gr);
            int    col  = bn + wn + nf * 8 + 2 * gc;
            float2 v0 = make_float2(acc[mf][nf][0], acc[mf][nf][1]);
            float2 v1 = make_float2(acc[mf][nf][2], acc[mf][nf][3]);
            *(float2*)&C[row0 * N + col]       = v0;
            *(float2*)&C[(row0 + 8) * N + col] = v1;
        }
}

// ---------------------------------------------------------------------------
// Causal flash attention, fp32 with packed f32x2 FMA (FFMA2).
// One thread per q row (128 rows / block), one block per (b, h, q-tile).
// q and o live in registers as f32x2 pairs; K/V tiles of 64 keys staged in
// smem, broadcast-read as 16B vectors (2 FFMA2 per LDS.128).
// qkv layout: [8192][3072], q|k|v at col offsets 0|1024|2048, head h at +h*64.
// ---------------------------------------------------------------------------
__global__ __launch_bounds__(128, 2) void flash_attn(
    const float* __restrict__ qkv, float* __restrict__ O)
{
    __shared__ __align__(16) float Ks[64][64];
    __shared__ __align__(16) float Vs[64][64];

    const int tid  = threadIdx.x;
    const int b    = blockIdx.z;
    const int h    = blockIdx.y;
    const int q0   = blockIdx.x * 128;
    const int qrow = q0 + tid;

    const float NEG_INF = -__int_as_float(0x7f800000);

    const float* qp = qkv + (size_t)(b * NS + qrow) * (3 * ND) + h * NDH;
    u64 q2[32];
    #pragma unroll
    for (int i = 0; i < 16; i++) {
        float4 v = *(const float4*)(qp + 4 * i);
        q2[2*i+0] = pack2(v.x * 0.125f, v.y * 0.125f);  // fold 1/sqrt(64)
        q2[2*i+1] = pack2(v.z * 0.125f, v.w * 0.125f);
    }
    u64 o2[32];
    #pragma unroll
    for (int i = 0; i < 32; i++) o2[i] = 0ull;   // bit pattern == (0.f, 0.f)
    float m = NEG_INF, l = 0.f;

    const int kend = q0 + 128;
    for (int kv0 = 0; kv0 < kend; kv0 += 64) {
        __syncthreads();
        #pragma unroll
        for (int i = 0; i < 8; i++) {
            int idx = tid + 128 * i;       // 0..1023
            int r = idx >> 4, c = (idx & 15) << 2;
            const float* kp = qkv + (size_t)(b * NS + kv0 + r) * (3 * ND) + ND + h * NDH + c;
            *(float4*)&Ks[r][c] = *(const float4*)kp;
            *(float4*)&Vs[r][c] = *(const float4*)(kp + ND);
        }
        __syncthreads();

        if (kv0 <= qrow) {
            #pragma unroll 1
            for (int jc = 0; jc < 64; jc += 16) {
                if (kv0 + jc > qrow) break;
                float s[16];
                #pragma unroll
                for (int jj = 0; jj < 16; jj++) {
                    const ulonglong2* kr = (const ulonglong2*)&Ks[jc + jj][0];
                    u64 accA = 0ull, accB = 0ull;       // two chains for ILP
                    #pragma unroll
                    for (int d4 = 0; d4 < 16; d4++) {
                        ulonglong2 kk = kr[d4];         // LDS.128 broadcast
                        accA = fma2(q2[2*d4+0], kk.x, accA);
                        accB = fma2(q2[2*d4+1], kk.y, accB);
                    }
                    float a0, a1, b0, b1;
                    unpack2(accA, a0, a1);
                    unpack2(accB, b0, b1);
                    float a = (a0 + a1) + (b0 + b1);
                    s[jj] = (kv0 + jc + jj <= qrow) ? a : NEG_INF;
                }
                float mx = m;
                #pragma unroll
                for (int jj = 0; jj < 16; jj++) mx = fmaxf(mx, s[jj]);
                float corr = __expf(m - mx);   // m=-inf first time -> 0
                m = mx;
                l *= corr;
                u64 corr2 = pack2(corr, corr);
                #pragma unroll
                for (int i = 0; i < 32; i++) o2[i] = mul2(o2[i], corr2);
                #pragma unroll
                for (int jj = 0; jj < 16; jj++) {
                    float p = __expf(s[jj] - m);   // masked: exp(-inf)=0
                    l += p;
                    u64 p2 = pack2(p, p);
                    const ulonglong2* vr = (const ulonglong2*)&Vs[jc + jj][0];
                    #pragma unroll
                    for (int d4 = 0; d4 < 16; d4++) {
                        ulonglong2 vv = vr[d4];     // LDS.128 broadcast
                        o2[2*d4+0] = fma2(p2, vv.x, o2[2*d4+0]);
                        o2[2*d4+1] = fma2(p2, vv.y, o2[2*d4+1]);
                    }
                }
            }
        }
    }

    const float inv = 1.f / l;
    float* op = O + (size_t)(b * NS + qrow) * ND + h * NDH;
    #pragma unroll
    for (int i = 0; i < 16; i++) {
        float x0, x1, x2, x3;
        unpack2(o2[2*i+0], x0, x1);
        unpack2(o2[2*i+1], x2, x3);
        float4 v = make_float4(x0 * inv, x1 * inv, x2 * inv, x3 * inv);
        *(float4*)(op + 4 * i) = v;
    }
}

// ---------------------------------------------------------------------------
// Launch: x -> qkv (tf32 gemm) -> flash attention -> out proj (tf32 gemm)
// Inputs (metadata order): [0]=x f32, [1]=mask (unused, causal known),
// [2]=W_qkv f32 [1024,3072], [3]=W_out f32 [1024,1024]. Output f32 [8,1024,1024].
// ---------------------------------------------------------------------------
extern "C" void kernel_launch(void* const* d_in, const int* in_sizes, int n_in,
                              void* d_out, int out_size)
{
    (void)in_sizes; (void)n_in; (void)out_size;
    const float* x    = (const float*)d_in[0];
    const float* Wqkv = (const float*)d_in[2];
    const float* Wout = (const float*)d_in[3];
    float* out = (float*)d_out;

    float *qkv_s = nullptr, *att_s = nullptr;
    cudaGetSymbolAddress((void**)&qkv_s, g_qkv);
    cudaGetSymbolAddress((void**)&att_s, g_att);

    // QKV projection: [8192,1024] @ [1024,3072]
    gemm_tf32<<<dim3(3 * ND / 128, ROWS / 128), 256>>>(x, Wqkv, qkv_s, ROWS, 3 * ND, ND);
    // Causal attention
    flash_attn<<<dim3(NS / 128, NH, NB), 128>>>(qkv_s, att_s);
    // Output projection: [8192,1024] @ [1024,1024]
    gemm_tf32<<<dim3(ND / 128, ROWS / 128), 256>>>(att_s, Wout, out, ROWS, ND, ND);
}

// round 4
// speedup vs baseline: 1.5745x; 1.5745x over previous
#include <cuda_runtime.h>
#include <cstdint>

#define NB 8
#define NS 1024
#define ND 1024
#define NH 16
#define NDH 64
#define ROWS (NB * NS)  // 8192

// Scratch (allocation-free rule: __device__ globals)
__device__ float g_qkv[(size_t)ROWS * 3 * ND];  // [8192][3072]
__device__ float g_att[(size_t)ROWS * ND];      // [8192][1024]

__device__ __forceinline__ uint32_t f2tf(float x) {
    uint32_t u;
    asm("cvt.rna.tf32.f32 %0, %1;" : "=r"(u) : "f"(x));
    return u;
}
__device__ __forceinline__ void cp_async16(void* smem, const void* gmem) {
    uint32_t s = (uint32_t)__cvta_generic_to_shared(smem);
    asm volatile("cp.async.cg.shared.global [%0], [%1], 16;\n" :: "r"(s), "l"(gmem));
}
__device__ __forceinline__ void cp_commit() { asm volatile("cp.async.commit_group;\n"); }
__device__ __forceinline__ void cp_wait0()  { asm volatile("cp.async.wait_group 0;\n"); }

#define MMA_TF32(acc, a, b) \
    asm volatile( \
        "mma.sync.aligned.m16n8k8.row.col.f32.tf32.tf32.f32 " \
        "{%0,%1,%2,%3}, {%4,%5,%6,%7}, {%8,%9}, {%0,%1,%2,%3};\n" \
        : "+f"(acc[0]), "+f"(acc[1]), "+f"(acc[2]), "+f"(acc[3]) \
        : "r"(a[0]), "r"(a[1]), "r"(a[2]), "r"(a[3]), \
          "r"(b[0]), "r"(b[1]))

// ---------------------------------------------------------------------------
// C[M,N] = A[M,K] @ B[K,N], all row-major fp32, TF32 tensor-core mma.
// (unchanged — measured: 403us for QKV proj, tensor=41.9%)
// ---------------------------------------------------------------------------
__global__ __launch_bounds__(256) void gemm_tf32(
    const float* __restrict__ A, const float* __restrict__ B,
    float* __restrict__ C, int M, int N, int K)
{
    constexpr int BM = 128, BN = 128, BK = 16;
    __shared__ __align__(16) float As[2][BM][BK + 4];
    __shared__ __align__(16) float Bs[2][BK][BN + 8];

    const int tid  = threadIdx.x;
    const int bm   = blockIdx.y * BM;
    const int bn   = blockIdx.x * BN;
    const int warp = tid >> 5, lane = tid & 31;
    const int wm   = (warp & 1) * 64;
    const int wn   = (warp >> 1) * 32;
    const int gr   = lane >> 2;
    const int gc   = lane & 3;

    float acc[4][4][4];
    #pragma unroll
    for (int mf = 0; mf < 4; mf++)
        #pragma unroll
        for (int nf = 0; nf < 4; nf++)
            #pragma unroll
            for (int i = 0; i < 4; i++)
                acc[mf][nf][i] = 0.f;

    auto load_tile = [&](int t, int buf) {
        #pragma unroll
        for (int i = 0; i < 2; i++) {
            int idx = tid + 256 * i;
            int ra = idx >> 2, ca = (idx & 3) << 2;
            cp_async16(&As[buf][ra][ca],
                       A + (size_t)(bm + ra) * K + t * BK + ca);
            int rb = idx >> 5, cb = (idx & 31) << 2;
            cp_async16(&Bs[buf][rb][cb],
                       B + (size_t)(t * BK + rb) * N + bn + cb);
        }
        cp_commit();
    };

    const int NT = K / BK;
    load_tile(0, 0);

    for (int t = 0; t < NT; t++) {
        const int buf = t & 1;
        cp_wait0();
        __syncthreads();
        if (t + 1 < NT) load_tile(t + 1, buf ^ 1);

        #pragma unroll
        for (int ks = 0; ks < BK; ks += 8) {
            uint32_t afr[4][4], bfr[4][2];
            #pragma unroll
            for (int mf = 0; mf < 4; mf++) {
                int row = wm + mf * 16;
                afr[mf][0] = f2tf(As[buf][row + gr    ][ks + gc    ]);
                afr[mf][1] = f2tf(As[buf][row + gr + 8][ks + gc    ]);
                afr[mf][2] = f2tf(As[buf][row + gr    ][ks + gc + 4]);
                afr[mf][3] = f2tf(As[buf][row + gr + 8][ks + gc + 4]);
            }
            #pragma unroll
            for (int nf = 0; nf < 4; nf++) {
                int col = wn + nf * 8 + gr;
                bfr[nf][0] = f2tf(Bs[buf][ks + gc    ][col]);
                bfr[nf][1] = f2tf(Bs[buf][ks + gc + 4][col]);
            }
            #pragma unroll
            for (int mf = 0; mf < 4; mf++)
                #pragma unroll
                for (int nf = 0; nf < 4; nf++)
                    MMA_TF32(acc[mf][nf], afr[mf], bfr[nf]);
        }
    }

    #pragma unroll
    for (int mf = 0; mf < 4; mf++)
        #pragma unroll
        for (int nf = 0; nf < 4; nf++) {
            size_t row0 = (size_t)(bm + wm + mf * 16 + gr);
            int    col  = bn + wn + nf * 8 + 2 * gc;
            float2 v0 = make_float2(acc[mf][nf][0], acc[mf][nf][1]);
            float2 v1 = make_float2(acc[mf][nf][2], acc[mf][nf][3]);
            *(float2*)&C[row0 * N + col]       = v0;
            *(float2*)&C[(row0 + 8) * N + col] = v1;
        }
}

// ---------------------------------------------------------------------------
// Tensor-core causal flash attention (TF32 m16n8k8).
// Block = 128 threads (4 warps), each warp owns 16 q rows -> 64 q rows/block.
// K/V staged in smem as tf32 bits (tiles of 32 keys, STS.128 vectorized);
// P routed through a per-warp smem buffer (STS.64) to reshape C->A frags.
// Bank math: K/V stride 72 (frag-load banks 8*gc+gr / 8*gc+gr: full-rank),
// P stride 36 (pa-load banks 4*gr+gc: full-rank). Conflict-free loads.
// ---------------------------------------------------------------------------
__global__ __launch_bounds__(128) void flash_attn_mma(
    const float* __restrict__ qkv, float* __restrict__ O)
{
    __shared__ __align__(16) uint32_t Ks[32][72];
    __shared__ __align__(16) uint32_t Vs[32][72];
    __shared__ __align__(16) uint32_t Ps[4][16][36];

    const int tid  = threadIdx.x;
    const int lane = tid & 31;
    const int w    = tid >> 5;
    const int gr   = lane >> 2;   // 0..7
    const int gc   = lane & 3;    // 0..3
    const int b    = blockIdx.z;
    const int h    = blockIdx.y;
    const int q0   = blockIdx.x * 64;

    const int rowA = q0 + w * 16 + gr;      // global q row (frag rows gr)
    const int rowB = rowA + 8;              // frag rows gr+8

    // ---- Load Q fragments (held for whole kernel), fold 1/sqrt(64) ----
    uint32_t qa[8][4];
    {
        const float* qp = qkv + (size_t)(b * NS) * (3 * ND) + h * NDH;
        #pragma unroll
        for (int ks = 0; ks < 8; ks++) {
            qa[ks][0] = f2tf(qp[(size_t)rowA * 3072 + ks * 8 + gc    ] * 0.125f);
            qa[ks][1] = f2tf(qp[(size_t)rowB * 3072 + ks * 8 + gc    ] * 0.125f);
            qa[ks][2] = f2tf(qp[(size_t)rowA * 3072 + ks * 8 + gc + 4] * 0.125f);
            qa[ks][3] = f2tf(qp[(size_t)rowB * 3072 + ks * 8 + gc + 4] * 0.125f);
        }
    }

    float o[8][4];
    #pragma unroll
    for (int nf = 0; nf < 8; nf++)
        #pragma unroll
        for (int i = 0; i < 4; i++) o[nf][i] = 0.f;
    float mA = -1e30f, mB = -1e30f, lA = 0.f, lB = 0.f;

    const int ntiles = (q0 + 64) / 32;   // causal: tiles fully above diag skipped
    for (int t = 0; t < ntiles; t++) {
        const int kv0 = t * 32;
        __syncthreads();   // protect smem reuse from previous iteration

        // ---- Stage K/V tile [32 keys x 64 dh] as tf32 bits (STS.128) ----
        #pragma unroll
        for (int i = 0; i < 4; i++) {
            int f = tid + 128 * i;          // 0..511 float4 slots
            int r = f >> 4, c4 = (f & 15) << 2;
            const float* kp = qkv + (size_t)(b * NS + kv0 + r) * 3072 + ND + h * NDH + c4;
            float4 kv_ = *(const float4*)kp;
            float4 vv_ = *(const float4*)(kp + ND);
            uint4 kt = make_uint4(f2tf(kv_.x), f2tf(kv_.y), f2tf(kv_.z), f2tf(kv_.w));
            uint4 vt = make_uint4(f2tf(vv_.x), f2tf(vv_.y), f2tf(vv_.z), f2tf(vv_.w));
            *(uint4*)&Ks[r][c4] = kt;
            *(uint4*)&Vs[r][c4] = vt;
        }
        __syncthreads();

        // Warp-level causal skip: this warp's rows all < kv0 -> fully masked
        if (kv0 > q0 + w * 16 + 15) continue;

        // ---- S = Q K^T : 4 n-frags (32 keys), accumulate over 8 k-steps ----
        float s[4][4];
        #pragma unroll
        for (int nf = 0; nf < 4; nf++) {
            #pragma unroll
            for (int i = 0; i < 4; i++) s[nf][i] = 0.f;
            #pragma unroll
            for (int ks = 0; ks < 8; ks++) {
                uint32_t bfr[2];
                bfr[0] = Ks[nf * 8 + gr][ks * 8 + gc    ];
                bfr[1] = Ks[nf * 8 + gr][ks * 8 + gc + 4];
                MMA_TF32(s[nf], qa[ks], bfr);
            }
        }

        // ---- causal mask (diagonal tiles only) ----
        if (kv0 + 31 > q0 + w * 16) {
            #pragma unroll
            for (int nf = 0; nf < 4; nf++) {
                int col = kv0 + nf * 8 + 2 * gc;
                if (col     > rowA) s[nf][0] = -1e30f;
                if (col + 1 > rowA) s[nf][1] = -1e30f;
                if (col     > rowB) s[nf][2] = -1e30f;
                if (col + 1 > rowB) s[nf][3] = -1e30f;
            }
        }

        // ---- online softmax ----
        float tmA = -1e30f, tmB = -1e30f;
        #pragma unroll
        for (int nf = 0; nf < 4; nf++) {
            tmA = fmaxf(tmA, fmaxf(s[nf][0], s[nf][1]));
            tmB = fmaxf(tmB, fmaxf(s[nf][2], s[nf][3]));
        }
        tmA = fmaxf(tmA, __shfl_xor_sync(0xffffffff, tmA, 1));
        tmA = fmaxf(tmA, __shfl_xor_sync(0xffffffff, tmA, 2));
        tmB = fmaxf(tmB, __shfl_xor_sync(0xffffffff, tmB, 1));
        tmB = fmaxf(tmB, __shfl_xor_sync(0xffffffff, tmB, 2));
        float nmA = fmaxf(mA, tmA), nmB = fmaxf(mB, tmB);
        float cA = __expf(mA - nmA), cB = __expf(mB - nmB);
        mA = nmA; mB = nmB;
        lA *= cA;  lB *= cB;
        #pragma unroll
        for (int nf = 0; nf < 8; nf++) {
            o[nf][0] *= cA; o[nf][1] *= cA;
            o[nf][2] *= cB; o[nf][3] *= cB;
        }
        #pragma unroll
        for (int nf = 0; nf < 4; nf++) {
            float p0 = __expf(s[nf][0] - mA);
            float p1 = __expf(s[nf][1] - mA);
            float p2 = __expf(s[nf][2] - mB);
            float p3 = __expf(s[nf][3] - mB);
            lA += p0 + p1;  lB += p2 + p3;
            uint2 pt0 = make_uint2(f2tf(p0), f2tf(p1));
            uint2 pt1 = make_uint2(f2tf(p2), f2tf(p3));
            *(uint2*)&Ps[w][gr    ][nf * 8 + 2 * gc] = pt0;   // STS.64
            *(uint2*)&Ps[w][gr + 8][nf * 8 + 2 * gc] = pt1;   // STS.64
        }
        __syncwarp();

        // ---- O += P V : k over 32 keys (4 steps), 8 n-frags (dh 64) ----
        #pragma unroll
        for (int ks = 0; ks < 4; ks++) {
            uint32_t pa[4];
            pa[0] = Ps[w][gr    ][ks * 8 + gc    ];
            pa[1] = Ps[w][gr + 8][ks * 8 + gc    ];
            pa[2] = Ps[w][gr    ][ks * 8 + gc + 4];
            pa[3] = Ps[w][gr + 8][ks * 8 + gc + 4];
            #pragma unroll
            for (int nf = 0; nf < 8; nf++) {
                uint32_t bfr[2];
                bfr[0] = Vs[ks * 8 + gc    ][nf * 8 + gr];
                bfr[1] = Vs[ks * 8 + gc + 4][nf * 8 + gr];
                MMA_TF32(o[nf], pa, bfr);
            }
        }
        __syncwarp();   // Ps reused next tile (warp-private)
    }

    // ---- finalize: row sums across the 4-lane group, write out ----
    lA += __shfl_xor_sync(0xffffffff, lA, 1);
    lA += __shfl_xor_sync(0xffffffff, lA, 2);
    lB += __shfl_xor_sync(0xffffffff, lB, 1);
    lB += __shfl_xor_sync(0xffffffff, lB, 2);
    const float iA = 1.f / lA, iB = 1.f / lB;

    float* opA = O + (size_t)(b * NS + rowA) * ND + h * NDH;
    float* opB = O + (size_t)(b * NS + rowB) * ND + h * NDH;
    #pragma unroll
    for (int nf = 0; nf < 8; nf++) {
        *(float2*)(opA + nf * 8 + 2 * gc) = make_float2(o[nf][0] * iA, o[nf][1] * iA);
        *(float2*)(opB + nf * 8 + 2 * gc) = make_float2(o[nf][2] * iB, o[nf][3] * iB);
    }
}

// ---------------------------------------------------------------------------
// Launch: x -> qkv (tf32 gemm) -> flash attention (tf32 mma) -> out proj
// ---------------------------------------------------------------------------
extern "C" void kernel_launch(void* const* d_in, const int* in_sizes, int n_in,
                              void* d_out, int out_size)
{
    (void)in_sizes; (void)n_in; (void)out_size;
    const float* x    = (const float*)d_in[0];
    const float* Wqkv = (const float*)d_in[2];
    const float* Wout = (const float*)d_in[3];
    float* out = (float*)d_out;

    float *qkv_s = nullptr, *att_s = nullptr;
    cudaGetSymbolAddress((void**)&qkv_s, g_qkv);
    cudaGetSymbolAddress((void**)&att_s, g_att);

    gemm_tf32<<<dim3(3 * ND / 128, ROWS / 128), 256>>>(x, Wqkv, qkv_s, ROWS, 3 * ND, ND);
    flash_attn_mma<<<dim3(NS / 64, NH, NB), 128>>>(qkv_s, att_s);
    gemm_tf32<<<dim3(ND / 128, ROWS / 128), 256>>>(att_s, Wout, out, ROWS, ND, ND);
}

// round 8
// speedup vs baseline: 1.6360x; 1.0390x over previous
#include <cuda_runtime.h>
#include <cstdint>

#define NB 8
#define NS 1024
#define ND 1024
#define NH 16
#define NDH 64
#define ROWS (NB * NS)  // 8192

// Scratch (allocation-free rule: __device__ globals)
__device__ float g_qkv[(size_t)ROWS * 3 * ND];  // [8192][3072]
__device__ float g_att[(size_t)ROWS * ND];      // [8192][1024]

__device__ __forceinline__ uint32_t f2tf(float x) {
    uint32_t u;
    asm("cvt.rna.tf32.f32 %0, %1;" : "=r"(u) : "f"(x));
    return u;
}
__device__ __forceinline__ void cp_async16(void* smem, const void* gmem) {
    uint32_t s = (uint32_t)__cvta_generic_to_shared(smem);
    asm volatile("cp.async.cg.shared.global [%0], [%1], 16;\n" :: "r"(s), "l"(gmem));
}
__device__ __forceinline__ void cp_commit() { asm volatile("cp.async.commit_group;\n"); }
__device__ __forceinline__ void cp_wait0()  { asm volatile("cp.async.wait_group 0;\n"); }

#define MMA_TF32(acc, a, b) \
    asm volatile( \
        "mma.sync.aligned.m16n8k8.row.col.f32.tf32.tf32.f32 " \
        "{%0,%1,%2,%3}, {%4,%5,%6,%7}, {%8,%9}, {%0,%1,%2,%3};\n" \
        : "+f"(acc[0]), "+f"(acc[1]), "+f"(acc[2]), "+f"(acc[3]) \
        : "r"(a[0]), "r"(a[1]), "r"(a[2]), "r"(a[3]), \
          "r"(b[0]), "r"(b[1]))

// ---------------------------------------------------------------------------
// C[M,N] = A[M,K] @ B[K,N], row-major fp32, TF32 m16n8k8.
// 128 threads (4 warps), warp tile 64x64 (round-4 measured config was 64x32
// at tensor=42%, issue=46% -> issue-bound; this raises mma issue fraction
// from 25% to 33% and makes the tensor pipe the binding resource).
// ---------------------------------------------------------------------------
__global__ __launch_bounds__(128, 2) void gemm_tf32(
    const float* __restrict__ A, const float* __restrict__ B,
    float* __restrict__ C, int M, int N, int K)
{
    constexpr int BM = 128, BN = 128, BK = 16;
    __shared__ __align__(16) float As[2][BM][BK + 4];   // stride 20: frag banks full-rank
    __shared__ __align__(16) float Bs[2][BK][BN + 8];   // stride 136: frag banks full-rank

    const int tid  = threadIdx.x;
    const int bm   = blockIdx.y * BM;
    const int bn   = blockIdx.x * BN;
    const int warp = tid >> 5, lane = tid & 31;
    const int wm   = (warp & 1) * 64;
    const int wn   = (warp >> 1) * 64;
    const int gr   = lane >> 2;
    const int gc   = lane & 3;

    float acc[4][8][4];
    #pragma unroll
    for (int mf = 0; mf < 4; mf++)
        #pragma unroll
        for (int nf = 0; nf < 8; nf++)
            #pragma unroll
            for (int i = 0; i < 4; i++)
                acc[mf][nf][i] = 0.f;

    auto load_tile = [&](int t, int buf) {
        #pragma unroll
        for (int i = 0; i < 4; i++) {
            int idx = tid + 128 * i;                 // 0..511
            int ra = idx >> 2, ca = (idx & 3) << 2;  // A: 128 rows x 4 float4
            cp_async16(&As[buf][ra][ca],
                       A + (size_t)(bm + ra) * K + t * BK + ca);
            int rb = idx >> 5, cb = (idx & 31) << 2; // B: 16 rows x 32 float4
            cp_async16(&Bs[buf][rb][cb],
                       B + (size_t)(t * BK + rb) * N + bn + cb);
        }
        cp_commit();
    };

    const int NT = K / BK;
    load_tile(0, 0);

    for (int t = 0; t < NT; t++) {
        const int buf = t & 1;
        cp_wait0();
        __syncthreads();
        if (t + 1 < NT) load_tile(t + 1, buf ^ 1);

        #pragma unroll
        for (int ks = 0; ks < BK; ks += 8) {
            uint32_t afr[4][4], bfr[8][2];
            #pragma unroll
            for (int mf = 0; mf < 4; mf++) {
                int row = wm + mf * 16;
                afr[mf][0] = f2tf(As[buf][row + gr    ][ks + gc    ]);
                afr[mf][1] = f2tf(As[buf][row + gr + 8][ks + gc    ]);
                afr[mf][2] = f2tf(As[buf][row + gr    ][ks + gc + 4]);
                afr[mf][3] = f2tf(As[buf][row + gr + 8][ks + gc + 4]);
            }
            #pragma unroll
            for (int nf = 0; nf < 8; nf++) {
                int col = wn + nf * 8 + gr;
                bfr[nf][0] = f2tf(Bs[buf][ks + gc    ][col]);
                bfr[nf][1] = f2tf(Bs[buf][ks + gc + 4][col]);
            }
            #pragma unroll
            for (int mf = 0; mf < 4; mf++)
                #pragma unroll
                for (int nf = 0; nf < 8; nf++)
                    MMA_TF32(acc[mf][nf], afr[mf], bfr[nf]);
        }
    }

    #pragma unroll
    for (int mf = 0; mf < 4; mf++)
        #pragma unroll
        for (int nf = 0; nf < 8; nf++) {
            size_t row0 = (size_t)(bm + wm + mf * 16 + gr);
            int    col  = bn + wn + nf * 8 + 2 * gc;
            float2 v0 = make_float2(acc[mf][nf][0], acc[mf][nf][1]);
            float2 v1 = make_float2(acc[mf][nf][2], acc[mf][nf][3]);
            *(float2*)&C[row0 * N + col]       = v0;
            *(float2*)&C[(row0 + 8) * N + col] = v1;
        }
}

// ---------------------------------------------------------------------------
// Tensor-core causal flash attention (TF32 m16n8k8). Unchanged from round 4
// (measured ~220us share). 4 warps x 16 q-rows, K/V tiles of 32 keys.
// ---------------------------------------------------------------------------
__global__ __launch_bounds__(128) void flash_attn_mma(
    const float* __restrict__ qkv, float* __restrict__ O)
{
    __shared__ __align__(16) uint32_t Ks[32][72];
    __shared__ __align__(16) uint32_t Vs[32][72];
    __shared__ __align__(16) uint32_t Ps[4][16][36];

    const int tid  = threadIdx.x;
    const int lane = tid & 31;
    const int w    = tid >> 5;
    const int gr   = lane >> 2;   // 0..7
    const int gc   = lane & 3;    // 0..3
    const int b    = blockIdx.z;
    const int h    = blockIdx.y;
    const int q0   = blockIdx.x * 64;

    const int rowA = q0 + w * 16 + gr;
    const int rowB = rowA + 8;

    uint32_t qa[8][4];
    {
        const float* qp = qkv + (size_t)(b * NS) * (3 * ND) + h * NDH;
        #pragma unroll
        for (int ks = 0; ks < 8; ks++) {
            qa[ks][0] = f2tf(qp[(size_t)rowA * 3072 + ks * 8 + gc    ] * 0.125f);
            qa[ks][1] = f2tf(qp[(size_t)rowB * 3072 + ks * 8 + gc    ] * 0.125f);
            qa[ks][2] = f2tf(qp[(size_t)rowA * 3072 + ks * 8 + gc + 4] * 0.125f);
            qa[ks][3] = f2tf(qp[(size_t)rowB * 3072 + ks * 8 + gc + 4] * 0.125f);
        }
    }

    float o[8][4];
    #pragma unroll
    for (int nf = 0; nf < 8; nf++)
        #pragma unroll
        for (int i = 0; i < 4; i++) o[nf][i] = 0.f;
    float mA = -1e30f, mB = -1e30f, lA = 0.f, lB = 0.f;

    const int ntiles = (q0 + 64) / 32;
    for (int t = 0; t < ntiles; t++) {
        const int kv0 = t * 32;
        __syncthreads();

        #pragma unroll
        for (int i = 0; i < 4; i++) {
            int f = tid + 128 * i;
            int r = f >> 4, c4 = (f & 15) << 2;
            const float* kp = qkv + (size_t)(b * NS + kv0 + r) * 3072 + ND + h * NDH + c4;
            float4 kv_ = *(const float4*)kp;
            float4 vv_ = *(const float4*)(kp + ND);
            uint4 kt = make_uint4(f2tf(kv_.x), f2tf(kv_.y), f2tf(kv_.z), f2tf(kv_.w));
            uint4 vt = make_uint4(f2tf(vv_.x), f2tf(vv_.y), f2tf(vv_.z), f2tf(vv_.w));
            *(uint4*)&Ks[r][c4] = kt;
            *(uint4*)&Vs[r][c4] = vt;
        }
        __syncthreads();

        if (kv0 > q0 + w * 16 + 15) continue;

        float s[4][4];
        #pragma unroll
        for (int nf = 0; nf < 4; nf++) {
            #pragma unroll
            for (int i = 0; i < 4; i++) s[nf][i] = 0.f;
            #pragma unroll
            for (int ks = 0; ks < 8; ks++) {
                uint32_t bfr[2];
                bfr[0] = Ks[nf * 8 + gr][ks * 8 + gc    ];
                bfr[1] = Ks[nf * 8 + gr][ks * 8 + gc + 4];
                MMA_TF32(s[nf], qa[ks], bfr);
            }
        }

        if (kv0 + 31 > q0 + w * 16) {
            #pragma unroll
            for (int nf = 0; nf < 4; nf++) {
                int col = kv0 + nf * 8 + 2 * gc;
                if (col     > rowA) s[nf][0] = -1e30f;
                if (col + 1 > rowA) s[nf][1] = -1e30f;
                if (col     > rowB) s[nf][2] = -1e30f;
                if (col + 1 > rowB) s[nf][3] = -1e30f;
            }
        }

        float tmA = -1e30f, tmB = -1e30f;
        #pragma unroll
        for (int nf = 0; nf < 4; nf++) {
            tmA = fmaxf(tmA, fmaxf(s[nf][0], s[nf][1]));
            tmB = fmaxf(tmB, fmaxf(s[nf][2], s[nf][3]));
        }
        tmA = fmaxf(tmA, __shfl_xor_sync(0xffffffff, tmA, 1));
        tmA = fmaxf(tmA, __shfl_xor_sync(0xffffffff, tmA, 2));
        tmB = fmaxf(tmB, __shfl_xor_sync(0xffffffff, tmB, 1));
        tmB = fmaxf(tmB, __shfl_xor_sync(0xffffffff, tmB, 2));
        float nmA = fmaxf(mA, tmA), nmB = fmaxf(mB, tmB);
        float cA = __expf(mA - nmA), cB = __expf(mB - nmB);
        mA = nmA; mB = nmB;
        lA *= cA;  lB *= cB;
        #pragma unroll
        for (int nf = 0; nf < 8; nf++) {
            o[nf][0] *= cA; o[nf][1] *= cA;
            o[nf][2] *= cB; o[nf][3] *= cB;
        }
        #pragma unroll
        for (int nf = 0; nf < 4; nf++) {
            float p0 = __expf(s[nf][0] - mA);
            float p1 = __expf(s[nf][1] - mA);
            float p2 = __expf(s[nf][2] - mB);
            float p3 = __expf(s[nf][3] - mB);
            lA += p0 + p1;  lB += p2 + p3;
            uint2 pt0 = make_uint2(f2tf(p0), f2tf(p1));
            uint2 pt1 = make_uint2(f2tf(p2), f2tf(p3));
            *(uint2*)&Ps[w][gr    ][nf * 8 + 2 * gc] = pt0;
            *(uint2*)&Ps[w][gr + 8][nf * 8 + 2 * gc] = pt1;
        }
        __syncwarp();

        #pragma unroll
        for (int ks = 0; ks < 4; ks++) {
            uint32_t pa[4];
            pa[0] = Ps[w][gr    ][ks * 8 + gc    ];
            pa[1] = Ps[w][gr + 8][ks * 8 + gc    ];
            pa[2] = Ps[w][gr    ][ks * 8 + gc + 4];
            pa[3] = Ps[w][gr + 8][ks * 8 + gc + 4];
            #pragma unroll
            for (int nf = 0; nf < 8; nf++) {
                uint32_t bfr[2];
                bfr[0] = Vs[ks * 8 + gc    ][nf * 8 + gr];
                bfr[1] = Vs[ks * 8 + gc + 4][nf * 8 + gr];
                MMA_TF32(o[nf], pa, bfr);
            }
        }
        __syncwarp();
    }

    lA += __shfl_xor_sync(0xffffffff, lA, 1);
    lA += __shfl_xor_sync(0xffffffff, lA, 2);
    lB += __shfl_xor_sync(0xffffffff, lB, 1);
    lB += __shfl_xor_sync(0xffffffff, lB, 2);
    const float iA = 1.f / lA, iB = 1.f / lB;

    float* opA = O + (size_t)(b * NS + rowA) * ND + h * NDH;
    float* opB = O + (size_t)(b * NS + rowB) * ND + h * NDH;
    #pragma unroll
    for (int nf = 0; nf < 8; nf++) {
        *(float2*)(opA + nf * 8 + 2 * gc) = make_float2(o[nf][0] * iA, o[nf][1] * iA);
        *(float2*)(opB + nf * 8 + 2 * gc) = make_float2(o[nf][2] * iB, o[nf][3] * iB);
    }
}

// ---------------------------------------------------------------------------
// Launch: x -> qkv (tf32 gemm) -> flash attention (tf32 mma) -> out proj
// ---------------------------------------------------------------------------
extern "C" void kernel_launch(void* const* d_in, const int* in_sizes, int n_in,
                              void* d_out, int out_size)
{
    (void)in_sizes; (void)n_in; (void)out_size;
    const float* x    = (const float*)d_in[0];
    const float* Wqkv = (const float*)d_in[2];
    const float* Wout = (const float*)d_in[3];
    float* out = (float*)d_out;

    float *qkv_s = nullptr, *att_s = nullptr;
    cudaGetSymbolAddress((void**)&qkv_s, g_qkv);
    cudaGetSymbolAddress((void**)&att_s, g_att);

    gemm_tf32<<<dim3(3 * ND / 128, ROWS / 128), 128>>>(x, Wqkv, qkv_s, ROWS, 3 * ND, ND);
    flash_attn_mma<<<dim3(NS / 64, NH, NB), 128>>>(qkv_s, att_s);
    gemm_tf32<<<dim3(ND / 128, ROWS / 128), 128>>>(att_s, Wout, out, ROWS, ND, ND);
}

// round 9
// speedup vs baseline: 1.6468x; 1.0066x over previous
#include <cuda_runtime.h>
#include <cstdint>

#define NB 8
#define NS 1024
#define ND 1024
#define NH 16
#define NDH 64
#define ROWS (NB * NS)  // 8192

// Scratch (allocation-free rule: __device__ globals)
__device__ float g_qkv[(size_t)ROWS * 3 * ND];  // [8192][3072]
__device__ float g_att[(size_t)ROWS * ND];      // [8192][1024]

__device__ __forceinline__ uint32_t f2tf(float x) {
    uint32_t u;
    asm("cvt.rna.tf32.f32 %0, %1;" : "=r"(u) : "f"(x));
    return u;
}
__device__ __forceinline__ void cp_async16(void* smem, const void* gmem) {
    uint32_t s = (uint32_t)__cvta_generic_to_shared(smem);
    asm volatile("cp.async.cg.shared.global [%0], [%1], 16;\n" :: "r"(s), "l"(gmem));
}
__device__ __forceinline__ void cp_commit() { asm volatile("cp.async.commit_group;\n"); }
template <int N>
__device__ __forceinline__ void cp_wait() { asm volatile("cp.async.wait_group %0;\n" :: "n"(N)); }

#define MMA_TF32(acc, a, b) \
    asm volatile( \
        "mma.sync.aligned.m16n8k8.row.col.f32.tf32.tf32.f32 " \
        "{%0,%1,%2,%3}, {%4,%5,%6,%7}, {%8,%9}, {%0,%1,%2,%3};\n" \
        : "+f"(acc[0]), "+f"(acc[1]), "+f"(acc[2]), "+f"(acc[3]) \
        : "r"(a[0]), "r"(a[1]), "r"(a[2]), "r"(a[3]), \
          "r"(b[0]), "r"(b[1]))

// ---------------------------------------------------------------------------
// C[M,N] = A[M,K] @ B[K,N], row-major fp32, TF32 m16n8k8.
// 128 threads (4 warps), warp tile 64x64, block tile 128x128, BK=16.
// Round-9 change: 4-stage cp.async pipeline (prefetch distance 3,
// wait_group<=2) via dynamic smem. Round-8 profile showed ~500cyc/tile of
// exposed latency with 1-deep prefetch (tensor 44.5%, issue 32%, occ 12%);
// 3-tile-deep prefetch hides the global load latency entirely.
// Stage = As[128][20] + Bs[16][136] floats = 18.9KB; 4 stages = 74KB dynamic.
// ---------------------------------------------------------------------------
#define GSTAGES 4
#define AS_STRIDE 20
#define BS_STRIDE 136
#define AS_STAGE (128 * AS_STRIDE)                 // floats per As stage
#define BS_STAGE (16 * BS_STRIDE)                  // floats per Bs stage
#define STAGE_FLOATS (AS_STAGE + BS_STAGE)
#define GEMM_SMEM_BYTES (GSTAGES * STAGE_FLOATS * 4)

__global__ __launch_bounds__(128, 2) void gemm_tf32(
    const float* __restrict__ A, const float* __restrict__ B,
    float* __restrict__ C, int M, int N, int K)
{
    constexpr int BM = 128, BN = 128, BK = 16;
    extern __shared__ __align__(16) float smem_dyn[];

    const int tid  = threadIdx.x;
    const int bm   = blockIdx.y * BM;
    const int bn   = blockIdx.x * BN;
    const int warp = tid >> 5, lane = tid & 31;
    const int wm   = (warp & 1) * 64;
    const int wn   = (warp >> 1) * 64;
    const int gr   = lane >> 2;
    const int gc   = lane & 3;

    float acc[4][8][4];
    #pragma unroll
    for (int mf = 0; mf < 4; mf++)
        #pragma unroll
        for (int nf = 0; nf < 8; nf++)
            #pragma unroll
            for (int i = 0; i < 4; i++)
                acc[mf][nf][i] = 0.f;

    auto As = [&](int buf, int r, int c) -> float* {
        return smem_dyn + buf * STAGE_FLOATS + r * AS_STRIDE + c;
    };
    auto Bs = [&](int buf, int r, int c) -> float* {
        return smem_dyn + buf * STAGE_FLOATS + AS_STAGE + r * BS_STRIDE + c;
    };

    auto load_tile = [&](int t, int buf) {
        #pragma unroll
        for (int i = 0; i < 4; i++) {
            int idx = tid + 128 * i;                 // 0..511
            int ra = idx >> 2, ca = (idx & 3) << 2;  // A: 128 rows x 4 float4
            cp_async16(As(buf, ra, ca),
                       A + (size_t)(bm + ra) * K + t * BK + ca);
            int rb = idx >> 5, cb = (idx & 31) << 2; // B: 16 rows x 32 float4
            cp_async16(Bs(buf, rb, cb),
                       B + (size_t)(t * BK + rb) * N + bn + cb);
        }
        cp_commit();
    };

    const int NT = K / BK;
    load_tile(0, 0);
    load_tile(1, 1);
    load_tile(2, 2);

    for (int t = 0; t < NT; t++) {
        const int buf = t & (GSTAGES - 1);
        cp_wait<GSTAGES - 2>();        // tile t's group complete (<=2 newer outstanding)
        __syncthreads();
        if (t + 3 < NT) load_tile(t + 3, (t + 3) & (GSTAGES - 1));

        #pragma unroll
        for (int ks = 0; ks < BK; ks += 8) {
            uint32_t afr[4][4], bfr[8][2];
            #pragma unroll
            for (int mf = 0; mf < 4; mf++) {
                int row = wm + mf * 16;
                afr[mf][0] = f2tf(*As(buf, row + gr,     ks + gc    ));
                afr[mf][1] = f2tf(*As(buf, row + gr + 8, ks + gc    ));
                afr[mf][2] = f2tf(*As(buf, row + gr,     ks + gc + 4));
                afr[mf][3] = f2tf(*As(buf, row + gr + 8, ks + gc + 4));
            }
            #pragma unroll
            for (int nf = 0; nf < 8; nf++) {
                int col = wn + nf * 8 + gr;
                bfr[nf][0] = f2tf(*Bs(buf, ks + gc,     col));
                bfr[nf][1] = f2tf(*Bs(buf, ks + gc + 4, col));
            }
            #pragma unroll
            for (int mf = 0; mf < 4; mf++)
                #pragma unroll
                for (int nf = 0; nf < 8; nf++)
                    MMA_TF32(acc[mf][nf], afr[mf], bfr[nf]);
        }
        __syncthreads();   // all warps done reading buf before it is refilled
    }

    #pragma unroll
    for (int mf = 0; mf < 4; mf++)
        #pragma unroll
        for (int nf = 0; nf < 8; nf++) {
            size_t row0 = (size_t)(bm + wm + mf * 16 + gr);
            int    col  = bn + wn + nf * 8 + 2 * gc;
            float2 v0 = make_float2(acc[mf][nf][0], acc[mf][nf][1]);
            float2 v1 = make_float2(acc[mf][nf][2], acc[mf][nf][3]);
            *(float2*)&C[row0 * N + col]       = v0;
            *(float2*)&C[(row0 + 8) * N + col] = v1;
        }
}

// ---------------------------------------------------------------------------
// Tensor-core causal flash attention (TF32 m16n8k8). Unchanged from round 4
// (measured ~215us share). 4 warps x 16 q-rows, K/V tiles of 32 keys.
// ---------------------------------------------------------------------------
__global__ __launch_bounds__(128) void flash_attn_mma(
    const float* __restrict__ qkv, float* __restrict__ O)
{
    __shared__ __align__(16) uint32_t Ks[32][72];
    __shared__ __align__(16) uint32_t Vs[32][72];
    __shared__ __align__(16) uint32_t Ps[4][16][36];

    const int tid  = threadIdx.x;
    const int lane = tid & 31;
    const int w    = tid >> 5;
    const int gr   = lane >> 2;   // 0..7
    const int gc   = lane & 3;    // 0..3
    const int b    = blockIdx.z;
    const int h    = blockIdx.y;
    const int q0   = blockIdx.x * 64;

    const int rowA = q0 + w * 16 + gr;
    const int rowB = rowA + 8;

    uint32_t qa[8][4];
    {
        const float* qp = qkv + (size_t)(b * NS) * (3 * ND) + h * NDH;
        #pragma unroll
        for (int ks = 0; ks < 8; ks++) {
            qa[ks][0] = f2tf(qp[(size_t)rowA * 3072 + ks * 8 + gc    ] * 0.125f);
            qa[ks][1] = f2tf(qp[(size_t)rowB * 3072 + ks * 8 + gc    ] * 0.125f);
            qa[ks][2] = f2tf(qp[(size_t)rowA * 3072 + ks * 8 + gc + 4] * 0.125f);
            qa[ks][3] = f2tf(qp[(size_t)rowB * 3072 + ks * 8 + gc + 4] * 0.125f);
        }
    }

    float o[8][4];
    #pragma unroll
    for (int nf = 0; nf < 8; nf++)
        #pragma unroll
        for (int i = 0; i < 4; i++) o[nf][i] = 0.f;
    float mA = -1e30f, mB = -1e30f, lA = 0.f, lB = 0.f;

    const int ntiles = (q0 + 64) / 32;
    for (int t = 0; t < ntiles; t++) {
        const int kv0 = t * 32;
        __syncthreads();

        #pragma unroll
        for (int i = 0; i < 4; i++) {
            int f = tid + 128 * i;
            int r = f >> 4, c4 = (f & 15) << 2;
            const float* kp = qkv + (size_t)(b * NS + kv0 + r) * 3072 + ND + h * NDH + c4;
            float4 kv_ = *(const float4*)kp;
            float4 vv_ = *(const float4*)(kp + ND);
            uint4 kt = make_uint4(f2tf(kv_.x), f2tf(kv_.y), f2tf(kv_.z), f2tf(kv_.w));
            uint4 vt = make_uint4(f2tf(vv_.x), f2tf(vv_.y), f2tf(vv_.z), f2tf(vv_.w));
            *(uint4*)&Ks[r][c4] = kt;
            *(uint4*)&Vs[r][c4] = vt;
        }
        __syncthreads();

        if (kv0 > q0 + w * 16 + 15) continue;

        float s[4][4];
        #pragma unroll
        for (int nf = 0; nf < 4; nf++) {
            #pragma unroll
            for (int i = 0; i < 4; i++) s[nf][i] = 0.f;
            #pragma unroll
            for (int ks = 0; ks < 8; ks++) {
                uint32_t bfr[2];
                bfr[0] = Ks[nf * 8 + gr][ks * 8 + gc    ];
                bfr[1] = Ks[nf * 8 + gr][ks * 8 + gc + 4];
                MMA_TF32(s[nf], qa[ks], bfr);
            }
        }

        if (kv0 + 31 > q0 + w * 16) {
            #pragma unroll
            for (int nf = 0; nf < 4; nf++) {
                int col = kv0 + nf * 8 + 2 * gc;
                if (col     > rowA) s[nf][0] = -1e30f;
                if (col + 1 > rowA) s[nf][1] = -1e30f;
                if (col     > rowB) s[nf][2] = -1e30f;
                if (col + 1 > rowB) s[nf][3] = -1e30f;
            }
        }

        float tmA = -1e30f, tmB = -1e30f;
        #pragma unroll
        for (int nf = 0; nf < 4; nf++) {
            tmA = fmaxf(tmA, fmaxf(s[nf][0], s[nf][1]));
            tmB = fmaxf(tmB, fmaxf(s[nf][2], s[nf][3]));
        }
        tmA = fmaxf(tmA, __shfl_xor_sync(0xffffffff, tmA, 1));
        tmA = fmaxf(tmA, __shfl_xor_sync(0xffffffff, tmA, 2));
        tmB = fmaxf(tmB, __shfl_xor_sync(0xffffffff, tmB, 1));
        tmB = fmaxf(tmB, __shfl_xor_sync(0xffffffff, tmB, 2));
        float nmA = fmaxf(mA, tmA), nmB = fmaxf(mB, tmB);
        float cA = __expf(mA - nmA), cB = __expf(mB - nmB);
        mA = nmA; mB = nmB;
        lA *= cA;  lB *= cB;
        #pragma unroll
        for (int nf = 0; nf < 8; nf++) {
            o[nf][0] *= cA; o[nf][1] *= cA;
            o[nf][2] *= cB; o[nf][3] *= cB;
        }
        #pragma unroll
        for (int nf = 0; nf < 4; nf++) {
            float p0 = __expf(s[nf][0] - mA);
            float p1 = __expf(s[nf][1] - mA);
            float p2 = __expf(s[nf][2] - mB);
            float p3 = __expf(s[nf][3] - mB);
            lA += p0 + p1;  lB += p2 + p3;
            uint2 pt0 = make_uint2(f2tf(p0), f2tf(p1));
            uint2 pt1 = make_uint2(f2tf(p2), f2tf(p3));
            *(uint2*)&Ps[w][gr    ][nf * 8 + 2 * gc] = pt0;
            *(uint2*)&Ps[w][gr + 8][nf * 8 + 2 * gc] = pt1;
        }
        __syncwarp();

        #pragma unroll
        for (int ks = 0; ks < 4; ks++) {
            uint32_t pa[4];
            pa[0] = Ps[w][gr    ][ks * 8 + gc    ];
            pa[1] = Ps[w][gr + 8][ks * 8 + gc    ];
            pa[2] = Ps[w][gr    ][ks * 8 + gc + 4];
            pa[3] = Ps[w][gr + 8][ks * 8 + gc + 4];
            #pragma unroll
            for (int nf = 0; nf < 8; nf++) {
                uint32_t bfr[2];
                bfr[0] = Vs[ks * 8 + gc    ][nf * 8 + gr];
                bfr[1] = Vs[ks * 8 + gc + 4][nf * 8 + gr];
                MMA_TF32(o[nf], pa, bfr);
            }
        }
        __syncwarp();
    }

    lA += __shfl_xor_sync(0xffffffff, lA, 1);
    lA += __shfl_xor_sync(0xffffffff, lA, 2);
    lB += __shfl_xor_sync(0xffffffff, lB, 1);
    lB += __shfl_xor_sync(0xffffffff, lB, 2);
    const float iA = 1.f / lA, iB = 1.f / lB;

    float* opA = O + (size_t)(b * NS + rowA) * ND + h * NDH;
    float* opB = O + (size_t)(b * NS + rowB) * ND + h * NDH;
    #pragma unroll
    for (int nf = 0; nf < 8; nf++) {
        *(float2*)(opA + nf * 8 + 2 * gc) = make_float2(o[nf][0] * iA, o[nf][1] * iA);
        *(float2*)(opB + nf * 8 + 2 * gc) = make_float2(o[nf][2] * iB, o[nf][3] * iB);
    }
}

// ---------------------------------------------------------------------------
// Launch: x -> qkv (tf32 gemm) -> flash attention (tf32 mma) -> out proj
// ---------------------------------------------------------------------------
extern "C" void kernel_launch(void* const* d_in, const int* in_sizes, int n_in,
                              void* d_out, int out_size)
{
    (void)in_sizes; (void)n_in; (void)out_size;
    const float* x    = (const float*)d_in[0];
    const float* Wqkv = (const float*)d_in[2];
    const float* Wout = (const float*)d_in[3];
    float* out = (float*)d_out;

    float *qkv_s = nullptr, *att_s = nullptr;
    cudaGetSymbolAddress((void**)&qkv_s, g_qkv);
    cudaGetSymbolAddress((void**)&att_s, g_att);

    // >48KB dynamic smem opt-in (host attribute set; graph-capture legal)
    static bool attr_done = false;
    if (!attr_done) {
        cudaFuncSetAttribute(gemm_tf32,
                             cudaFuncAttributeMaxDynamicSharedMemorySize,
                             GEMM_SMEM_BYTES);
        attr_done = true;
    }

    gemm_tf32<<<dim3(3 * ND / 128, ROWS / 128), 128, GEMM_SMEM_BYTES>>>(
        x, Wqkv, qkv_s, ROWS, 3 * ND, ND);
    flash_attn_mma<<<dim3(NS / 64, NH, NB), 128>>>(qkv_s, att_s);
    gemm_tf32<<<dim3(ND / 128, ROWS / 128), 128, GEMM_SMEM_BYTES>>>(
        att_s, Wout, out, ROWS, ND, ND);
}

// round 10
// speedup vs baseline: 1.7023x; 1.0337x over previous
#include <cuda_runtime.h>
#include <cstdint>

#define NB 8
#define NS 1024
#define ND 1024
#define NH 16
#define NDH 64
#define ROWS (NB * NS)  // 8192

// Scratch (allocation-free rule: __device__ globals)
__device__ float    g_qkv[(size_t)ROWS * 3 * ND];   // QKV GEMM output (fp32)
__device__ float    g_att[(size_t)ROWS * ND];       // attention output (fp32 -> tf32 in place)
__device__ uint32_t g_xt  [(size_t)ROWS * ND];      // x pre-rounded to tf32 bits
__device__ uint32_t g_wqkv[(size_t)ND * 3 * ND];    // W_qkv pre-rounded
__device__ uint32_t g_wout[(size_t)ND * ND];        // W_out pre-rounded

__device__ __forceinline__ uint32_t f2tf(float x) {
    uint32_t u;
    asm("cvt.rna.tf32.f32 %0, %1;" : "=r"(u) : "f"(x));
    return u;
}
__device__ __forceinline__ void cp_async16(void* smem, const void* gmem) {
    uint32_t s = (uint32_t)__cvta_generic_to_shared(smem);
    asm volatile("cp.async.cg.shared.global [%0], [%1], 16;\n" :: "r"(s), "l"(gmem));
}
__device__ __forceinline__ void cp_commit() { asm volatile("cp.async.commit_group;\n"); }
template <int N>
__device__ __forceinline__ void cp_wait() { asm volatile("cp.async.wait_group %0;\n" :: "n"(N)); }

#define MMA_TF32(acc, a, b) \
    asm volatile( \
        "mma.sync.aligned.m16n8k8.row.col.f32.tf32.tf32.f32 " \
        "{%0,%1,%2,%3}, {%4,%5,%6,%7}, {%8,%9}, {%0,%1,%2,%3};\n" \
        : "+f"(acc[0]), "+f"(acc[1]), "+f"(acc[2]), "+f"(acc[3]) \
        : "r"(a[0]), "r"(a[1]), "r"(a[2]), "r"(a[3]), \
          "r"(b[0]), "r"(b[1]))

// ---------------------------------------------------------------------------
// Elementwise tf32 pre-round (fp32 -> tf32 bit pattern). Memory-bound, ~5-10us
// per tensor. Applying cvt.rna once here is bit-identical to converting at
// every smem read (what rounds 2-9 did), so rel_err is unchanged.
// ---------------------------------------------------------------------------
__global__ void round_tf32(const float4* __restrict__ in,
                           uint4* __restrict__ out, int n4)
{
    int i = blockIdx.x * blockDim.x + threadIdx.x;
    if (i < n4) {
        float4 v = in[i];
        out[i] = make_uint4(f2tf(v.x), f2tf(v.y), f2tf(v.z), f2tf(v.w));
    }
}

// ---------------------------------------------------------------------------
// C[M,N] = A[M,K] @ B[K,N]; A,B are PRE-ROUNDED tf32 bits (uint32), C fp32.
// 128 threads (4 warps), warp tile 64x64, block tile 128x128, BK=16,
// 4-stage cp.async pipeline.
// Round-10 change: CVT removed from the hot loop (inputs pre-rounded).
// Round-9 profile: tensor 44.7%, issue 33.1% -- stalls were the LDS->CVT->MMA
// chain with only 2 warps/SMSP (reg-capped). Inner loop is now 32 LDS + 32 MMA
// per ks-step; chain shortens 50->29cyc and 1/3 of issue slots are freed.
// ---------------------------------------------------------------------------
#define GSTAGES 4
#define AS_STRIDE 20
#define BS_STRIDE 136
#define AS_STAGE (128 * AS_STRIDE)
#define BS_STAGE (16 * BS_STRIDE)
#define STAGE_WORDS (AS_STAGE + BS_STAGE)
#define GEMM_SMEM_BYTES (GSTAGES * STAGE_WORDS * 4)

__global__ __launch_bounds__(128, 2) void gemm_tf32(
    const uint32_t* __restrict__ A, const uint32_t* __restrict__ B,
    float* __restrict__ C, int M, int N, int K)
{
    constexpr int BM = 128, BN = 128, BK = 16;
    extern __shared__ __align__(16) uint32_t smem_dyn[];

    const int tid  = threadIdx.x;
    const int bm   = blockIdx.y * BM;
    const int bn   = blockIdx.x * BN;
    const int warp = tid >> 5, lane = tid & 31;
    const int wm   = (warp & 1) * 64;
    const int wn   = (warp >> 1) * 64;
    const int gr   = lane >> 2;
    const int gc   = lane & 3;

    float acc[4][8][4];
    #pragma unroll
    for (int mf = 0; mf < 4; mf++)
        #pragma unroll
        for (int nf = 0; nf < 8; nf++)
            #pragma unroll
            for (int i = 0; i < 4; i++)
                acc[mf][nf][i] = 0.f;

    auto As = [&](int buf, int r, int c) -> uint32_t* {
        return smem_dyn + buf * STAGE_WORDS + r * AS_STRIDE + c;
    };
    auto Bs = [&](int buf, int r, int c) -> uint32_t* {
        return smem_dyn + buf * STAGE_WORDS + AS_STAGE + r * BS_STRIDE + c;
    };

    auto load_tile = [&](int t, int buf) {
        #pragma unroll
        for (int i = 0; i < 4; i++) {
            int idx = tid + 128 * i;                 // 0..511
            int ra = idx >> 2, ca = (idx & 3) << 2;  // A: 128 rows x 4 uint4
            cp_async16(As(buf, ra, ca),
                       A + (size_t)(bm + ra) * K + t * BK + ca);
            int rb = idx >> 5, cb = (idx & 31) << 2; // B: 16 rows x 32 uint4
            cp_async16(Bs(buf, rb, cb),
                       B + (size_t)(t * BK + rb) * N + bn + cb);
        }
        cp_commit();
    };

    const int NT = K / BK;
    load_tile(0, 0);
    load_tile(1, 1);
    load_tile(2, 2);

    for (int t = 0; t < NT; t++) {
        const int buf = t & (GSTAGES - 1);
        cp_wait<GSTAGES - 2>();
        __syncthreads();
        if (t + 3 < NT) load_tile(t + 3, (t + 3) & (GSTAGES - 1));

        #pragma unroll
        for (int ks = 0; ks < BK; ks += 8) {
            uint32_t afr[4][4], bfr[8][2];
            #pragma unroll
            for (int mf = 0; mf < 4; mf++) {
                int row = wm + mf * 16;
                afr[mf][0] = *As(buf, row + gr,     ks + gc    );
                afr[mf][1] = *As(buf, row + gr + 8, ks + gc    );
                afr[mf][2] = *As(buf, row + gr,     ks + gc + 4);
                afr[mf][3] = *As(buf, row + gr + 8, ks + gc + 4);
            }
            #pragma unroll
            for (int nf = 0; nf < 8; nf++) {
                int col = wn + nf * 8 + gr;
                bfr[nf][0] = *Bs(buf, ks + gc,     col);
                bfr[nf][1] = *Bs(buf, ks + gc + 4, col);
            }
            #pragma unroll
            for (int mf = 0; mf < 4; mf++)
                #pragma unroll
                for (int nf = 0; nf < 8; nf++)
                    MMA_TF32(acc[mf][nf], afr[mf], bfr[nf]);
        }
        __syncthreads();
    }

    #pragma unroll
    for (int mf = 0; mf < 4; mf++)
        #pragma unroll
        for (int nf = 0; nf < 8; nf++) {
            size_t row0 = (size_t)(bm + wm + mf * 16 + gr);
            int    col  = bn + wn + nf * 8 + 2 * gc;
            float2 v0 = make_float2(acc[mf][nf][0], acc[mf][nf][1]);
            float2 v1 = make_float2(acc[mf][nf][2], acc[mf][nf][3]);
            *(float2*)&C[row0 * N + col]       = v0;
            *(float2*)&C[(row0 + 8) * N + col] = v1;
        }
}

// ---------------------------------------------------------------------------
// Tensor-core causal flash attention (TF32 m16n8k8). Unchanged from round 4
// (measured ~215us share). 4 warps x 16 q-rows, K/V tiles of 32 keys.
// ---------------------------------------------------------------------------
__global__ __launch_bounds__(128) void flash_attn_mma(
    const float* __restrict__ qkv, float* __restrict__ O)
{
    __shared__ __align__(16) uint32_t Ks[32][72];
    __shared__ __align__(16) uint32_t Vs[32][72];
    __shared__ __align__(16) uint32_t Ps[4][16][36];

    const int tid  = threadIdx.x;
    const int lane = tid & 31;
    const int w    = tid >> 5;
    const int gr   = lane >> 2;   // 0..7
    const int gc   = lane & 3;    // 0..3
    const int b    = blockIdx.z;
    const int h    = blockIdx.y;
    const int q0   = blockIdx.x * 64;

    const int rowA = q0 + w * 16 + gr;
    const int rowB = rowA + 8;

    uint32_t qa[8][4];
    {
        const float* qp = qkv + (size_t)(b * NS) * (3 * ND) + h * NDH;
        #pragma unroll
        for (int ks = 0; ks < 8; ks++) {
            qa[ks][0] = f2tf(qp[(size_t)rowA * 3072 + ks * 8 + gc    ] * 0.125f);
            qa[ks][1] = f2tf(qp[(size_t)rowB * 3072 + ks * 8 + gc    ] * 0.125f);
            qa[ks][2] = f2tf(qp[(size_t)rowA * 3072 + ks * 8 + gc + 4] * 0.125f);
            qa[ks][3] = f2tf(qp[(size_t)rowB * 3072 + ks * 8 + gc + 4] * 0.125f);
        }
    }

    float o[8][4];
    #pragma unroll
    for (int nf = 0; nf < 8; nf++)
        #pragma unroll
        for (int i = 0; i < 4; i++) o[nf][i] = 0.f;
    float mA = -1e30f, mB = -1e30f, lA = 0.f, lB = 0.f;

    const int ntiles = (q0 + 64) / 32;
    for (int t = 0; t < ntiles; t++) {
        const int kv0 = t * 32;
        __syncthreads();

        #pragma unroll
        for (int i = 0; i < 4; i++) {
            int f = tid + 128 * i;
            int r = f >> 4, c4 = (f & 15) << 2;
            const float* kp = qkv + (size_t)(b * NS + kv0 + r) * 3072 + ND + h * NDH + c4;
            float4 kv_ = *(const float4*)kp;
            float4 vv_ = *(const float4*)(kp + ND);
            uint4 kt = make_uint4(f2tf(kv_.x), f2tf(kv_.y), f2tf(kv_.z), f2tf(kv_.w));
            uint4 vt = make_uint4(f2tf(vv_.x), f2tf(vv_.y), f2tf(vv_.z), f2tf(vv_.w));
            *(uint4*)&Ks[r][c4] = kt;
            *(uint4*)&Vs[r][c4] = vt;
        }
        __syncthreads();

        if (kv0 > q0 + w * 16 + 15) continue;

        float s[4][4];
        #pragma unroll
        for (int nf = 0; nf < 4; nf++) {
            #pragma unroll
            for (int i = 0; i < 4; i++) s[nf][i] = 0.f;
            #pragma unroll
            for (int ks = 0; ks < 8; ks++) {
                uint32_t bfr[2];
                bfr[0] = Ks[nf * 8 + gr][ks * 8 + gc    ];
                bfr[1] = Ks[nf * 8 + gr][ks * 8 + gc + 4];
                MMA_TF32(s[nf], qa[ks], bfr);
            }
        }

        if (kv0 + 31 > q0 + w * 16) {
            #pragma unroll
            for (int nf = 0; nf < 4; nf++) {
                int col = kv0 + nf * 8 + 2 * gc;
                if (col     > rowA) s[nf][0] = -1e30f;
                if (col + 1 > rowA) s[nf][1] = -1e30f;
                if (col     > rowB) s[nf][2] = -1e30f;
                if (col + 1 > rowB) s[nf][3] = -1e30f;
            }
        }

        float tmA = -1e30f, tmB = -1e30f;
        #pragma unroll
        for (int nf = 0; nf < 4; nf++) {
            tmA = fmaxf(tmA, fmaxf(s[nf][0], s[nf][1]));
            tmB = fmaxf(tmB, fmaxf(s[nf][2], s[nf][3]));
        }
        tmA = fmaxf(tmA, __shfl_xor_sync(0xffffffff, tmA, 1));
        tmA = fmaxf(tmA, __shfl_xor_sync(0xffffffff, tmA, 2));
        tmB = fmaxf(tmB, __shfl_xor_sync(0xffffffff, tmB, 1));
        tmB = fmaxf(tmB, __shfl_xor_sync(0xffffffff, tmB, 2));
        float nmA = fmaxf(mA, tmA), nmB = fmaxf(mB, tmB);
        float cA = __expf(mA - nmA), cB = __expf(mB - nmB);
        mA = nmA; mB = nmB;
        lA *= cA;  lB *= cB;
        #pragma unroll
        for (int nf = 0; nf < 8; nf++) {
            o[nf][0] *= cA; o[nf][1] *= cA;
            o[nf][2] *= cB; o[nf][3] *= cB;
        }
        #pragma unroll
        for (int nf = 0; nf < 4; nf++) {
            float p0 = __expf(s[nf][0] - mA);
            float p1 = __expf(s[nf][1] - mA);
            float p2 = __expf(s[nf][2] - mB);
            float p3 = __expf(s[nf][3] - mB);
            lA += p0 + p1;  lB += p2 + p3;
            uint2 pt0 = make_uint2(f2tf(p0), f2tf(p1));
            uint2 pt1 = make_uint2(f2tf(p2), f2tf(p3));
            *(uint2*)&Ps[w][gr    ][nf * 8 + 2 * gc] = pt0;
            *(uint2*)&Ps[w][gr + 8][nf * 8 + 2 * gc] = pt1;
        }
        __syncwarp();

        #pragma unroll
        for (int ks = 0; ks < 4; ks++) {
            uint32_t pa[4];
            pa[0] = Ps[w][gr    ][ks * 8 + gc    ];
            pa[1] = Ps[w][gr + 8][ks * 8 + gc    ];
            pa[2] = Ps[w][gr    ][ks * 8 + gc + 4];
            pa[3] = Ps[w][gr + 8][ks * 8 + gc + 4];
            #pragma unroll
            for (int nf = 0; nf < 8; nf++) {
                uint32_t bfr[2];
                bfr[0] = Vs[ks * 8 + gc    ][nf * 8 + gr];
                bfr[1] = Vs[ks * 8 + gc + 4][nf * 8 + gr];
                MMA_TF32(o[nf], pa, bfr);
            }
        }
        __syncwarp();
    }

    lA += __shfl_xor_sync(0xffffffff, lA, 1);
    lA += __shfl_xor_sync(0xffffffff, lA, 2);
    lB += __shfl_xor_sync(0xffffffff, lB, 1);
    lB += __shfl_xor_sync(0xffffffff, lB, 2);
    const float iA = 1.f / lA, iB = 1.f / lB;

    float* opA = O + (size_t)(b * NS + rowA) * ND + h * NDH;
    float* opB = O + (size_t)(b * NS + rowB) * ND + h * NDH;
    #pragma unroll
    for (int nf = 0; nf < 8; nf++) {
        *(float2*)(opA + nf * 8 + 2 * gc) = make_float2(o[nf][0] * iA, o[nf][1] * iA);
        *(float2*)(opB + nf * 8 + 2 * gc) = make_float2(o[nf][2] * iB, o[nf][3] * iB);
    }
}

// ---------------------------------------------------------------------------
// Launch: pre-round inputs -> qkv gemm -> flash attention -> round att
//         -> out-proj gemm
// ---------------------------------------------------------------------------
extern "C" void kernel_launch(void* const* d_in, const int* in_sizes, int n_in,
                              void* d_out, int out_size)
{
    (void)in_sizes; (void)n_in; (void)out_size;
    const float* x    = (const float*)d_in[0];
    const float* Wqkv = (const float*)d_in[2];
    const float* Wout = (const float*)d_in[3];
    float* out = (float*)d_out;

    float    *qkv_s = nullptr, *att_s = nullptr;
    uint32_t *xt_s = nullptr, *wqkv_s = nullptr, *wout_s = nullptr;
    cudaGetSymbolAddress((void**)&qkv_s,  g_qkv);
    cudaGetSymbolAddress((void**)&att_s,  g_att);
    cudaGetSymbolAddress((void**)&xt_s,   g_xt);
    cudaGetSymbolAddress((void**)&wqkv_s, g_wqkv);
    cudaGetSymbolAddress((void**)&wout_s, g_wout);

    static bool attr_done = false;
    if (!attr_done) {
        cudaFuncSetAttribute(gemm_tf32,
                             cudaFuncAttributeMaxDynamicSharedMemorySize,
                             GEMM_SMEM_BYTES);
        attr_done = true;
    }

    const int n4_x  = ROWS * ND / 4;        // 2.1M
    const int n4_wq = ND * 3 * ND / 4;      // 786K
    const int n4_wo = ND * ND / 4;          // 262K

    round_tf32<<<(n4_x  + 255) / 256, 256>>>((const float4*)x,    (uint4*)xt_s,   n4_x);
    round_tf32<<<(n4_wq + 255) / 256, 256>>>((const float4*)Wqkv, (uint4*)wqkv_s, n4_wq);
    round_tf32<<<(n4_wo + 255) / 256, 256>>>((const float4*)Wout, (uint4*)wout_s, n4_wo);

    gemm_tf32<<<dim3(3 * ND / 128, ROWS / 128), 128, GEMM_SMEM_BYTES>>>(
        xt_s, wqkv_s, qkv_s, ROWS, 3 * ND, ND);

    flash_attn_mma<<<dim3(NS / 64, NH, NB), 128>>>(qkv_s, att_s);

    // round attention output in place (read fp32, write tf32 bits)
    round_tf32<<<(n4_x + 255) / 256, 256>>>((const float4*)att_s, (uint4*)att_s, n4_x);

    gemm_tf32<<<dim3(ND / 128, ROWS / 128), 128, GEMM_SMEM_BYTES>>>(
        (const uint32_t*)att_s, wout_s, out, ROWS, ND, ND);
}

// round 16
// speedup vs baseline: 1.9036x; 1.1182x over previous
#include <cuda_runtime.h>
#include <cstdint>

#define NB 8
#define NS 1024
#define ND 1024
#define NH 16
#define NDH 64
#define ROWS (NB * NS)  // 8192

// Scratch (allocation-free rule: __device__ globals)
__device__ float    g_qkv [(size_t)ROWS * 3 * ND];  // QKV GEMM out (fp32)
__device__ float    g_att [(size_t)ROWS * ND];      // attention out (fp32 -> tf32 bits in place)
__device__ uint32_t g_xt  [(size_t)ROWS * ND];      // x tf32 bits [8192][1024]
__device__ uint32_t g_wqkvT[(size_t)3 * ND * ND];   // W_qkv^T tf32 bits [3072][1024]
__device__ uint32_t g_woutT[(size_t)ND * ND];       // W_out^T tf32 bits [1024][1024]

__device__ __forceinline__ uint32_t f2tf(float x) {
    uint32_t u;
    asm("cvt.rna.tf32.f32 %0, %1;" : "=r"(u) : "f"(x));
    return u;
}
__device__ __forceinline__ uint32_t smem_u32(const void* p) {
    return (uint32_t)__cvta_generic_to_shared(p);
}
__device__ __forceinline__ void cp_async16_s(uint32_t smem, const void* gmem) {
    asm volatile("cp.async.cg.shared.global [%0], [%1], 16;\n" :: "r"(smem), "l"(gmem));
}
__device__ __forceinline__ void cp_commit() { asm volatile("cp.async.commit_group;\n"); }
template <int N>
__device__ __forceinline__ void cp_wait() { asm volatile("cp.async.wait_group %0;\n" :: "n"(N)); }

#define MMA_TF32(acc, a, b) \
    asm volatile( \
        "mma.sync.aligned.m16n8k8.row.col.f32.tf32.tf32.f32 " \
        "{%0,%1,%2,%3}, {%4,%5,%6,%7}, {%8,%9}, {%0,%1,%2,%3};\n" \
        : "+f"(acc[0]), "+f"(acc[1]), "+f"(acc[2]), "+f"(acc[3]) \
        : "r"(a[0]), "r"(a[1]), "r"(a[2]), "r"(a[3]), \
          "r"(b[0]), "r"(b[1]))

// ldmatrix x4 on 32-bit data: each 8x8 b16 tile == 8x4 tf32 block with thread
// mapping (t/4, t%4) -- exactly the m16n8k8 tf32 fragment distribution.
#define LDSM_X4(r0, r1, r2, r3, addr) \
    asm volatile("ldmatrix.sync.aligned.m8n8.x4.shared.b16 {%0,%1,%2,%3}, [%4];" \
        : "=r"(r0), "=r"(r1), "=r"(r2), "=r"(r3) : "r"(addr))

// ---------------------------------------------------------------------------
// Prologue A: elementwise fp32 -> tf32 bits (bit-identical to per-use cvt.rna)
// ---------------------------------------------------------------------------
__global__ void round_tf32(const float4* __restrict__ in, uint4* __restrict__ out, int n4)
{
    int i = blockIdx.x * blockDim.x + threadIdx.x;
    if (i < n4) {
        float4 v = in[i];
        out[i] = make_uint4(f2tf(v.x), f2tf(v.y), f2tf(v.z), f2tf(v.w));
    }
}

// ---------------------------------------------------------------------------
// Prologue B: transpose + round. in[R][C] fp32 -> out[C][R] tf32 bits.
// ---------------------------------------------------------------------------
__global__ void transpose_round(const float* __restrict__ in, uint32_t* __restrict__ out,
                                int R, int C)
{
    __shared__ float tile[32][33];
    int c0 = blockIdx.x * 32, r0 = blockIdx.y * 32;
    int tx = threadIdx.x, ty = threadIdx.y;   // 32 x 8
    #pragma unroll
    for (int j = 0; j < 32; j += 8)
        tile[ty + j][tx] = in[(size_t)(r0 + ty + j) * C + c0 + tx];
    __syncthreads();
    #pragma unroll
    for (int j = 0; j < 32; j += 8)
        out[(size_t)(c0 + ty + j) * R + r0 + tx] = f2tf(tile[tx][ty + j]);
}

// ---------------------------------------------------------------------------
// C[M,N] = A[M,K] @ Bt[N,K]^T; A,Bt pre-rounded tf32 bits, C fp32.
// 128 threads (4 warps), warp tile 64x64, block tile 128x128, BK=16,
// 4-stage cp.async ring (prefetch distance 3, single barrier per tile).
// Fragment loads via ldmatrix.x4 (A: 1/mf, B: 1/nf-pair) instead of 32
// scalar LDS per ks-step. B staged [N][K] (weights pre-transposed in the
// prologue) so B-frags use non-trans ldmatrix.
// Tail iterations (no trailing load committed) use wait_group 0 -- wait<2>
// alone does not prove tile t's group complete once commits stop.
// ---------------------------------------------------------------------------
#define GSTAGES 4
#define ROW_W 20                                  // words per smem row (16 + 4 pad)
#define TILE_WORDS (128 * ROW_W)                  // per operand per stage
#define A_ST_BYTES (TILE_WORDS * 4)               // 10240
#define ST_BYTES (2 * A_ST_BYTES)                 // 20480
#define GEMM_SMEM (GSTAGES * ST_BYTES)            // 81920

__global__ __launch_bounds__(128, 2) void gemm_tf32(
    const uint32_t* __restrict__ A, const uint32_t* __restrict__ Bt,
    float* __restrict__ C, int M, int N, int K)
{
    constexpr int BM = 128, BN = 128, BK = 16;
    extern __shared__ __align__(16) uint32_t smem_dyn[];
    const uint32_t sbase = smem_u32(smem_dyn);

    const int tid  = threadIdx.x;
    const int bm   = blockIdx.y * BM;
    const int bn   = blockIdx.x * BN;
    const int warp = tid >> 5, lane = tid & 31;
    const int wm   = (warp & 1) * 64;
    const int wn   = (warp >> 1) * 64;
    const int gr   = lane >> 2;
    const int gc   = lane & 3;

    float acc[4][8][4];
    #pragma unroll
    for (int mf = 0; mf < 4; mf++)
        #pragma unroll
        for (int nf = 0; nf < 8; nf++)
            #pragma unroll
            for (int i = 0; i < 4; i++)
                acc[mf][nf][i] = 0.f;

    // ldmatrix per-lane base offsets (bytes within a stage)
    // A tiles: t0 rows+0/col0, t1 rows+8/col0, t2 rows+0/col4, t3 rows+8/col4
    const uint32_t aOff =
        ((wm + (lane & 7) + ((lane >> 3) & 1) * 8) * ROW_W + ((lane >> 4) & 1) * 4) * 4;
    // B tiles: t0 n+0/col0, t1 n+0/col4, t2 n+8/col0, t3 n+8/col4
    const uint32_t bOff = A_ST_BYTES +
        ((wn + (lane & 7) + ((lane >> 4) & 1) * 8) * ROW_W + ((lane >> 3) & 1) * 4) * 4;

    auto load_tile = [&](int t, int buf) {
        const uint32_t st = sbase + buf * ST_BYTES;
        const int k0 = t * BK;
        #pragma unroll
        for (int i = 0; i < 4; i++) {                 // A: 512 16B chunks
            int idx = tid + 128 * i;
            int r = idx >> 2, c = (idx & 3) << 2;     // c in elems
            cp_async16_s(st + (r * ROW_W + c) * 4,
                         A + (size_t)(bm + r) * K + k0 + c);
        }
        #pragma unroll
        for (int i = 0; i < 4; i++) {                 // Bt: 512 16B chunks
            int idx = tid + 128 * i;
            int r = idx >> 2, c = (idx & 3) << 2;
            cp_async16_s(st + A_ST_BYTES + (r * ROW_W + c) * 4,
                         Bt + (size_t)(bn + r) * K + k0 + c);
        }
        cp_commit();
    };

    const int NT = K / BK;
    load_tile(0, 0);
    load_tile(1, 1);
    load_tile(2, 2);

    for (int t = 0; t < NT; t++) {
        const int buf = t & (GSTAGES - 1);
        if (t + 3 < NT) cp_wait<GSTAGES - 2>();   // steady state: 2 newer groups pending
        else            cp_wait<0>();             // tail: commits stopped -> drain all
        __syncthreads();               // all warps done with buf's previous contents
        if (t + 3 < NT) load_tile(t + 3, (t + 3) & (GSTAGES - 1));

        const uint32_t aBase = sbase + buf * ST_BYTES + aOff;
        const uint32_t bBase = sbase + buf * ST_BYTES + bOff;

        #pragma unroll
        for (int ks = 0; ks < BK; ks += 8) {
            uint32_t afr[4][4], bfr[8][2];
            #pragma unroll
            for (int mf = 0; mf < 4; mf++)
                LDSM_X4(afr[mf][0], afr[mf][1], afr[mf][2], afr[mf][3],
                        aBase + mf * (16 * ROW_W * 4) + ks * 4);
            #pragma unroll
            for (int p = 0; p < 4; p++)
                LDSM_X4(bfr[2*p][0], bfr[2*p][1], bfr[2*p+1][0], bfr[2*p+1][1],
                        bBase + p * (16 * ROW_W * 4) + ks * 4);
            #pragma unroll
            for (int mf = 0; mf < 4; mf++)
                #pragma unroll
                for (int nf = 0; nf < 8; nf++)
                    MMA_TF32(acc[mf][nf], afr[mf], bfr[nf]);
        }
    }

    #pragma unroll
    for (int mf = 0; mf < 4; mf++)
        #pragma unroll
        for (int nf = 0; nf < 8; nf++) {
            size_t row0 = (size_t)(bm + wm + mf * 16 + gr);
            int    col  = bn + wn + nf * 8 + 2 * gc;
            float2 v0 = make_float2(acc[mf][nf][0], acc[mf][nf][1]);
            float2 v1 = make_float2(acc[mf][nf][2], acc[mf][nf][3]);
            *(float2*)&C[row0 * N + col]       = v0;
            *(float2*)&C[(row0 + 8) * N + col] = v1;
        }
}

// ---------------------------------------------------------------------------
// Tensor-core causal flash attention (TF32 m16n8k8). Unchanged (measured
// ~215us share). 4 warps x 16 q-rows, K/V tiles of 32 keys.
// ---------------------------------------------------------------------------
__global__ __launch_bounds__(128) void flash_attn_mma(
    const float* __restrict__ qkv, float* __restrict__ O)
{
    __shared__ __align__(16) uint32_t Ks[32][72];
    __shared__ __align__(16) uint32_t Vs[32][72];
    __shared__ __align__(16) uint32_t Ps[4][16][36];

    const int tid  = threadIdx.x;
    const int lane = tid & 31;
    const int w    = tid >> 5;
    const int gr   = lane >> 2;
    const int gc   = lane & 3;
    const int b    = blockIdx.z;
    const int h    = blockIdx.y;
    const int q0   = blockIdx.x * 64;

    const int rowA = q0 + w * 16 + gr;
    const int rowB = rowA + 8;

    uint32_t qa[8][4];
    {
        const float* qp = qkv + (size_t)(b * NS) * (3 * ND) + h * NDH;
        #pragma unroll
        for (int ks = 0; ks < 8; ks++) {
            qa[ks][0] = f2tf(qp[(size_t)rowA * 3072 + ks * 8 + gc    ] * 0.125f);
            qa[ks][1] = f2tf(qp[(size_t)rowB * 3072 + ks * 8 + gc    ] * 0.125f);
            qa[ks][2] = f2tf(qp[(size_t)rowA * 3072 + ks * 8 + gc + 4] * 0.125f);
            qa[ks][3] = f2tf(qp[(size_t)rowB * 3072 + ks * 8 + gc + 4] * 0.125f);
        }
    }

    float o[8][4];
    #pragma unroll
    for (int nf = 0; nf < 8; nf++)
        #pragma unroll
        for (int i = 0; i < 4; i++) o[nf][i] = 0.f;
    float mA = -1e30f, mB = -1e30f, lA = 0.f, lB = 0.f;

    const int ntiles = (q0 + 64) / 32;
    for (int t = 0; t < ntiles; t++) {
        const int kv0 = t * 32;
        __syncthreads();

        #pragma unroll
        for (int i = 0; i < 4; i++) {
            int f = tid + 128 * i;
            int r = f >> 4, c4 = (f & 15) << 2;
            const float* kp = qkv + (size_t)(b * NS + kv0 + r) * 3072 + ND + h * NDH + c4;
            float4 kv_ = *(const float4*)kp;
            float4 vv_ = *(const float4*)(kp + ND);
            uint4 kt = make_uint4(f2tf(kv_.x), f2tf(kv_.y), f2tf(kv_.z), f2tf(kv_.w));
            uint4 vt = make_uint4(f2tf(vv_.x), f2tf(vv_.y), f2tf(vv_.z), f2tf(vv_.w));
            *(uint4*)&Ks[r][c4] = kt;
            *(uint4*)&Vs[r][c4] = vt;
        }
        __syncthreads();

        if (kv0 > q0 + w * 16 + 15) continue;

        float s[4][4];
        #pragma unroll
        for (int nf = 0; nf < 4; nf++) {
            #pragma unroll
            for (int i = 0; i < 4; i++) s[nf][i] = 0.f;
            #pragma unroll
            for (int ks = 0; ks < 8; ks++) {
                uint32_t bfr[2];
                bfr[0] = Ks[nf * 8 + gr][ks * 8 + gc    ];
                bfr[1] = Ks[nf * 8 + gr][ks * 8 + gc + 4];
                MMA_TF32(s[nf], qa[ks], bfr);
            }
        }

        if (kv0 + 31 > q0 + w * 16) {
            #pragma unroll
            for (int nf = 0; nf < 4; nf++) {
                int col = kv0 + nf * 8 + 2 * gc;
                if (col     > rowA) s[nf][0] = -1e30f;
                if (col + 1 > rowA) s[nf][1] = -1e30f;
                if (col     > rowB) s[nf][2] = -1e30f;
                if (col + 1 > rowB) s[nf][3] = -1e30f;
            }
        }

        float tmA = -1e30f, tmB = -1e30f;
        #pragma unroll
        for (int nf = 0; nf < 4; nf++) {
            tmA = fmaxf(tmA, fmaxf(s[nf][0], s[nf][1]));
            tmB = fmaxf(tmB, fmaxf(s[nf][2], s[nf][3]));
        }
        tmA = fmaxf(tmA, __shfl_xor_sync(0xffffffff, tmA, 1));
        tmA = fmaxf(tmA, __shfl_xor_sync(0xffffffff, tmA, 2));
        tmB = fmaxf(tmB, __shfl_xor_sync(0xffffffff, tmB, 1));
        tmB = fmaxf(tmB, __shfl_xor_sync(0xffffffff, tmB, 2));
        float nmA = fmaxf(mA, tmA), nmB = fmaxf(mB, tmB);
        float cA = __expf(mA - nmA), cB = __expf(mB - nmB);
        mA = nmA; mB = nmB;
        lA *= cA;  lB *= cB;
        #pragma unroll
        for (int nf = 0; nf < 8; nf++) {
            o[nf][0] *= cA; o[nf][1] *= cA;
            o[nf][2] *= cB; o[nf][3] *= cB;
        }
        #pragma unroll
        for (int nf = 0; nf < 4; nf++) {
            float p0 = __expf(s[nf][0] - mA);
            float p1 = __expf(s[nf][1] - mA);
            float p2 = __expf(s[nf][2] - mB);
            float p3 = __expf(s[nf][3] - mB);
            lA += p0 + p1;  lB += p2 + p3;
            uint2 pt0 = make_uint2(f2tf(p0), f2tf(p1));
            uint2 pt1 = make_uint2(f2tf(p2), f2tf(p3));
            *(uint2*)&Ps[w][gr    ][nf * 8 + 2 * gc] = pt0;
            *(uint2*)&Ps[w][gr + 8][nf * 8 + 2 * gc] = pt1;
        }
        __syncwarp();

        #pragma unroll
        for (int ks = 0; ks < 4; ks++) {
            uint32_t pa[4];
            pa[0] = Ps[w][gr    ][ks * 8 + gc    ];
            pa[1] = Ps[w][gr + 8][ks * 8 + gc    ];
            pa[2] = Ps[w][gr    ][ks * 8 + gc + 4];
            pa[3] = Ps[w][gr + 8][ks * 8 + gc + 4];
            #pragma unroll
            for (int nf = 0; nf < 8; nf++) {
                uint32_t bfr[2];
                bfr[0] = Vs[ks * 8 + gc    ][nf * 8 + gr];
                bfr[1] = Vs[ks * 8 + gc + 4][nf * 8 + gr];
                MMA_TF32(o[nf], pa, bfr);
            }
        }
        __syncwarp();
    }

    lA += __shfl_xor_sync(0xffffffff, lA, 1);
    lA += __shfl_xor_sync(0xffffffff, lA, 2);
    lB += __shfl_xor_sync(0xffffffff, lB, 1);
    lB += __shfl_xor_sync(0xffffffff, lB, 2);
    const float iA = 1.f / lA, iB = 1.f / lB;

    float* opA = O + (size_t)(b * NS + rowA) * ND + h * NDH;
    float* opB = O + (size_t)(b * NS + rowB) * ND + h * NDH;
    #pragma unroll
    for (int nf = 0; nf < 8; nf++) {
        *(float2*)(opA + nf * 8 + 2 * gc) = make_float2(o[nf][0] * iA, o[nf][1] * iA);
        *(float2*)(opB + nf * 8 + 2 * gc) = make_float2(o[nf][2] * iB, o[nf][3] * iB);
    }
}

// ---------------------------------------------------------------------------
// Launch: round x / transpose+round weights -> QKV gemm (ldmatrix) ->
// flash attention -> round att -> out-proj gemm
// ---------------------------------------------------------------------------
extern "C" void kernel_launch(void* const* d_in, const int* in_sizes, int n_in,
                              void* d_out, int out_size)
{
    (void)in_sizes; (void)n_in; (void)out_size;
    const float* x    = (const float*)d_in[0];
    const float* Wqkv = (const float*)d_in[2];
    const float* Wout = (const float*)d_in[3];
    float* out = (float*)d_out;

    float    *qkv_s = nullptr, *att_s = nullptr;
    uint32_t *xt_s = nullptr, *wqkvT_s = nullptr, *woutT_s = nullptr;
    cudaGetSymbolAddress((void**)&qkv_s,   g_qkv);
    cudaGetSymbolAddress((void**)&att_s,   g_att);
    cudaGetSymbolAddress((void**)&xt_s,    g_xt);
    cudaGetSymbolAddress((void**)&wqkvT_s, g_wqkvT);
    cudaGetSymbolAddress((void**)&woutT_s, g_woutT);

    static bool attr_done = false;
    if (!attr_done) {
        cudaFuncSetAttribute(gemm_tf32,
                             cudaFuncAttributeMaxDynamicSharedMemorySize, GEMM_SMEM);
        attr_done = true;
    }

    const int n4_x = ROWS * ND / 4;

    round_tf32<<<(n4_x + 255) / 256, 256>>>((const float4*)x, (uint4*)xt_s, n4_x);
    transpose_round<<<dim3(3 * ND / 32, ND / 32), dim3(32, 8)>>>(Wqkv, wqkvT_s, ND, 3 * ND);
    transpose_round<<<dim3(ND / 32, ND / 32), dim3(32, 8)>>>(Wout, woutT_s, ND, ND);

    // QKV projection: [8192,1024] @ [1024,3072]^T-staged
    gemm_tf32<<<dim3(3 * ND / 128, ROWS / 128), 128, GEMM_SMEM>>>(
        xt_s, wqkvT_s, qkv_s, ROWS, 3 * ND, ND);

    flash_attn_mma<<<dim3(NS / 64, NH, NB), 128>>>(qkv_s, att_s);

    // round attention output in place (A operand of out-proj)
    round_tf32<<<(n4_x + 255) / 256, 256>>>((const float4*)att_s, (uint4*)att_s, n4_x);

    // Output projection: [8192,1024] @ [1024,1024]^T-staged
    gemm_tf32<<<dim3(ND / 128, ROWS / 128), 128, GEMM_SMEM>>>(
        (const uint32_t*)att_s, woutT_s, out, ROWS, ND, ND);
}